// round 1
// baseline (speedup 1.0000x reference)
#include <cuda_runtime.h>
#include <mma.h>
#include <math.h>

using namespace nvcuda;

#define NROWS 8192
#define DIM 512

// Scratch (module-load allocated; no cudaMalloc anywhere)
__device__ float g_Q [NROWS*DIM];
__device__ float g_K [NROWS*DIM];
__device__ float g_V [NROWS*DIM];
__device__ float g_XR[NROWS*DIM];
__device__ float g_H [NROWS*DIM];

typedef wmma::fragment<wmma::matrix_a,16,16,8,wmma::precision::tf32,wmma::row_major> FragA;
typedef wmma::fragment<wmma::matrix_b,16,16,8,wmma::precision::tf32,wmma::row_major> FragB;
typedef wmma::fragment<wmma::matrix_b,16,16,8,wmma::precision::tf32,wmma::col_major> FragBT;
typedef wmma::fragment<wmma::accumulator,16,16,8,float> FragC;

// ---------------------------------------------------------------------------
// Small GEMMs (M=8192, N=512, K=512): C = act(A @ B + bias), tf32x3 accuracy.
// BM=64, BN=64, BK=32, 256 threads, warp grid 4(M) x 2(N).
// ---------------------------------------------------------------------------
template<int ACT>
__global__ void __launch_bounds__(256) gemm_x3_kernel(
    const float* __restrict__ A, const float* __restrict__ B,
    const float* __restrict__ bias, float* __restrict__ C)
{
    __shared__ float As[64][40];
    __shared__ float Bs[32][72];
    __shared__ float Cs[64][72];

    const int tid = threadIdx.x;
    const int w = tid >> 5, wm = w >> 1, wn = w & 1;
    const int bm = blockIdx.x * 64, bn = blockIdx.y * 64;

    FragC acc[2];
    wmma::fill_fragment(acc[0], 0.f);
    wmma::fill_fragment(acc[1], 0.f);

    const int ra = tid >> 3, ca = (tid & 7) * 4;    // A: 32 rows/pass, 2 passes
    const int rb = tid >> 4, cb = (tid & 15) * 4;   // B: 16 rows/pass, 2 passes

    for (int kt = 0; kt < DIM; kt += 32) {
        #pragma unroll
        for (int p = 0; p < 2; p++) {
            *(float4*)&As[ra + p*32][ca] =
                *(const float4*)&A[(size_t)(bm + ra + p*32)*DIM + kt + ca];
            *(float4*)&Bs[rb + p*16][cb] =
                *(const float4*)&B[(size_t)(kt + rb + p*16)*DIM + bn + cb];
        }
        __syncthreads();
        #pragma unroll
        for (int ks = 0; ks < 4; ks++) {
            FragA ar, ah, al;
            wmma::load_matrix_sync(ar, &As[wm*16][ks*8], 40);
            #pragma unroll
            for (int i = 0; i < ar.num_elements; i++) {
                float v = ar.x[i];
                float h = wmma::__float_to_tf32(v);
                ah.x[i] = h;
                al.x[i] = wmma::__float_to_tf32(v - h);
            }
            #pragma unroll
            for (int nf = 0; nf < 2; nf++) {
                FragB br, bh, bl;
                wmma::load_matrix_sync(br, &Bs[ks*8][wn*32 + nf*16], 72);
                #pragma unroll
                for (int i = 0; i < br.num_elements; i++) {
                    float v = br.x[i];
                    float h = wmma::__float_to_tf32(v);
                    bh.x[i] = h;
                    bl.x[i] = wmma::__float_to_tf32(v - h);
                }
                wmma::mma_sync(acc[nf], ah, bh, acc[nf]);
                wmma::mma_sync(acc[nf], al, bh, acc[nf]);
                wmma::mma_sync(acc[nf], ah, bl, acc[nf]);
            }
        }
        __syncthreads();
    }

    wmma::store_matrix_sync(&Cs[wm*16][wn*32],      acc[0], 72, wmma::mem_row_major);
    wmma::store_matrix_sync(&Cs[wm*16][wn*32 + 16], acc[1], 72, wmma::mem_row_major);
    __syncthreads();

    for (int idx = tid; idx < 64*64; idx += 256) {
        int r = idx >> 6, c = idx & 63;
        float v = Cs[r][c] + bias[bn + c];
        if (ACT == 1) v = 0.5f * v * (1.0f + erff(v * 0.70710678118654752f));
        C[(size_t)(bm + r)*DIM + bn + c] = v;
    }
}

// ---------------------------------------------------------------------------
// Fused retention: O = (D .* (Q @ K^T)) @ V without materializing inter.
// One CTA per 64-row Q block; 256 threads, 8 warps.
// Warp grid: S tile (64x64): 4(M) x 2(N of 32);  O tile (64x512): 4(M) x 2(N of 256).
// Dynamic SMEM: Qfull 64x520 + Ks 64x40 + Ss 64x72 + Vs 16x520 = 195072 B.
// ---------------------------------------------------------------------------
__global__ void __launch_bounds__(256) retention_kernel(
    const float* __restrict__ Q, const float* __restrict__ Kmat,
    const float* __restrict__ V, const float* __restrict__ D,
    float* __restrict__ O)
{
    extern __shared__ float sm[];
    float (*Qf)[520] = (float(*)[520])(sm);            // 33280 floats
    float (*Ks)[40]  = (float(*)[40]) (sm + 33280);    //  2560
    float (*Ss)[72]  = (float(*)[72]) (sm + 35840);    //  4608
    float (*Vs)[520] = (float(*)[520])(sm + 40448);    //  8320

    const int tid = threadIdx.x;
    const int w = tid >> 5, wm = w >> 1, wn = w & 1;
    const int i0 = blockIdx.x * 64;

    // Load the whole Q tile (64 x 512) once.
    #pragma unroll
    for (int p = 0; p < 32; p++) {
        int idx = tid + p*256;            // 8192 float4s
        int r = idx >> 7, c4 = (idx & 127) * 4;
        *(float4*)&Qf[r][c4] = *(const float4*)&Q[(size_t)(i0 + r)*DIM + c4];
    }

    FragC o[16];
    #pragma unroll
    for (int i = 0; i < 16; i++) wmma::fill_fragment(o[i], 0.f);
    __syncthreads();

    const int ra = tid >> 3, ca = (tid & 7) * 4;

    for (int j0 = 0; j0 < NROWS; j0 += 64) {
        // ---- S = Q_tile @ K_j^T  (64x64) ----
        FragC s[2];
        wmma::fill_fragment(s[0], 0.f);
        wmma::fill_fragment(s[1], 0.f);
        for (int kt = 0; kt < DIM; kt += 32) {
            #pragma unroll
            for (int p = 0; p < 2; p++)
                *(float4*)&Ks[ra + p*32][ca] =
                    *(const float4*)&Kmat[(size_t)(j0 + ra + p*32)*DIM + kt + ca];
            __syncthreads();
            #pragma unroll
            for (int ks = 0; ks < 4; ks++) {
                FragA a;
                wmma::load_matrix_sync(a, &Qf[wm*16][kt + ks*8], 520);
                #pragma unroll
                for (int i = 0; i < a.num_elements; i++)
                    a.x[i] = wmma::__float_to_tf32(a.x[i]);
                #pragma unroll
                for (int sn = 0; sn < 2; sn++) {
                    FragBT b;   // B[k][n] = K[j0+n][k] -> col-major on Ks rows
                    wmma::load_matrix_sync(b, &Ks[wn*32 + sn*16][ks*8], 40);
                    #pragma unroll
                    for (int i = 0; i < b.num_elements; i++)
                        b.x[i] = wmma::__float_to_tf32(b.x[i]);
                    wmma::mma_sync(s[sn], a, b, s[sn]);
                }
            }
            __syncthreads();
        }
        wmma::store_matrix_sync(&Ss[wm*16][wn*32],      s[0], 72, wmma::mem_row_major);
        wmma::store_matrix_sync(&Ss[wm*16][wn*32 + 16], s[1], 72, wmma::mem_row_major);
        __syncthreads();

        // ---- S *= D tile (elementwise, D streamed from HBM exactly once) ----
        #pragma unroll
        for (int q = 0; q < 16; q++) {
            int idx = tid + q*256;
            int r = idx >> 6, c = idx & 63;
            Ss[r][c] *= D[(size_t)(i0 + r)*NROWS + j0 + c];
        }
        __syncthreads();

        // ---- O += S_d (64x64) @ V_j (64x512) ----
        #pragma unroll 1
        for (int k2 = 0; k2 < 64; k2 += 16) {
            #pragma unroll
            for (int p = 0; p < 8; p++) {
                int idx = tid + p*256;    // 2048 float4s (16 x 512)
                int r = idx >> 7, c4 = (idx & 127) * 4;
                *(float4*)&Vs[r][c4] =
                    *(const float4*)&V[(size_t)(j0 + k2 + r)*DIM + c4];
            }
            __syncthreads();
            #pragma unroll
            for (int ks = 0; ks < 2; ks++) {
                FragA a;
                wmma::load_matrix_sync(a, &Ss[wm*16][k2 + ks*8], 72);
                #pragma unroll
                for (int i = 0; i < a.num_elements; i++)
                    a.x[i] = wmma::__float_to_tf32(a.x[i]);
                #pragma unroll
                for (int nf = 0; nf < 16; nf++) {
                    FragB b;
                    wmma::load_matrix_sync(b, &Vs[ks*8][wn*256 + nf*16], 520);
                    #pragma unroll
                    for (int i = 0; i < b.num_elements; i++)
                        b.x[i] = wmma::__float_to_tf32(b.x[i]);
                    wmma::mma_sync(o[nf], a, b, o[nf]);
                }
            }
            __syncthreads();
        }
    }

    #pragma unroll
    for (int nf = 0; nf < 16; nf++)
        wmma::store_matrix_sync(&O[(size_t)(i0 + wm*16)*DIM + wn*256 + nf*16],
                                o[nf], DIM, wmma::mem_row_major);
}

// ---------------------------------------------------------------------------
// GroupNorm over 16 groups of 32 channels, per row, in-place on d_out.
// ---------------------------------------------------------------------------
__global__ void groupnorm_kernel(float* __restrict__ out,
                                 const float* __restrict__ gamma,
                                 const float* __restrict__ beta)
{
    __shared__ float buf[512];
    __shared__ float smu[16], siv[16];
    const int row = blockIdx.x;
    const int tid = threadIdx.x;  // 256
    float* p = out + (size_t)row * DIM;
    buf[tid]       = p[tid];
    buf[tid + 256] = p[tid + 256];
    __syncthreads();
    if (tid < 16) {
        float s = 0.f, s2 = 0.f;
        #pragma unroll
        for (int c = 0; c < 32; c++) {
            float v = buf[tid*32 + c];
            s += v; s2 += v*v;
        }
        float mu  = s  * (1.f/32.f);
        float var = s2 * (1.f/32.f) - mu*mu;
        smu[tid] = mu;
        siv[tid] = rsqrtf(var + 1e-5f);
    }
    __syncthreads();
    #pragma unroll
    for (int q = 0; q < 2; q++) {
        int c = tid + q*256;
        int g = c >> 5;
        p[c] = (buf[c] - smu[g]) * siv[g] * gamma[c] + beta[c];
    }
}

// ---------------------------------------------------------------------------
extern "C" void kernel_launch(void* const* d_in, const int* in_sizes, int n_in,
                              void* d_out, int out_size)
{
    const float* x     = (const float*)d_in[0];
    const float* D     = (const float*)d_in[1];
    const float* Wq    = (const float*)d_in[2];
    const float* bq    = (const float*)d_in[3];
    const float* Wk    = (const float*)d_in[4];
    const float* bk    = (const float*)d_in[5];
    const float* Wv    = (const float*)d_in[6];
    const float* bv    = (const float*)d_in[7];
    const float* Wf    = (const float*)d_in[8];
    const float* bf    = (const float*)d_in[9];
    const float* Wp    = (const float*)d_in[10];
    const float* bp    = (const float*)d_in[11];
    const float* gamma = (const float*)d_in[12];
    const float* beta  = (const float*)d_in[13];
    float* out = (float*)d_out;

    float *Q, *K, *V, *XR, *H;
    cudaGetSymbolAddress((void**)&Q,  g_Q);
    cudaGetSymbolAddress((void**)&K,  g_K);
    cudaGetSymbolAddress((void**)&V,  g_V);
    cudaGetSymbolAddress((void**)&XR, g_XR);
    cudaGetSymbolAddress((void**)&H,  g_H);

    const int RET_SMEM = 195072;  // bytes of dynamic shared memory
    cudaFuncSetAttribute(retention_kernel,
                         cudaFuncAttributeMaxDynamicSharedMemorySize, RET_SMEM);

    dim3 gs(NROWS/64, DIM/64);   // 128 x 8
    gemm_x3_kernel<0><<<gs, 256>>>(x, Wq, bq, Q);
    gemm_x3_kernel<0><<<gs, 256>>>(x, Wk, bk, K);
    gemm_x3_kernel<0><<<gs, 256>>>(x, Wv, bv, V);

    retention_kernel<<<NROWS/64, 256, RET_SMEM>>>(Q, K, V, D, XR);

    gemm_x3_kernel<1><<<gs, 256>>>(XR, Wf, bf, H);    // + exact GELU
    gemm_x3_kernel<0><<<gs, 256>>>(H,  Wp, bp, out);

    groupnorm_kernel<<<NROWS, 256>>>(out, gamma, beta);
}

// round 2
// speedup vs baseline: 1.0936x; 1.0936x over previous
#include <cuda_runtime.h>
#include <mma.h>
#include <math.h>

using namespace nvcuda;

#define NROWS 8192
#define DIM 512

// Scratch (module-load allocated; no cudaMalloc anywhere)
__device__ float g_Q [NROWS*DIM];
__device__ float g_K [NROWS*DIM];
__device__ float g_V [NROWS*DIM];
__device__ float g_XR[NROWS*DIM];
__device__ float g_H [NROWS*DIM];

typedef wmma::fragment<wmma::matrix_a,16,16,8,wmma::precision::tf32,wmma::row_major> FragA;
typedef wmma::fragment<wmma::matrix_b,16,16,8,wmma::precision::tf32,wmma::row_major> FragB;
typedef wmma::fragment<wmma::matrix_b,16,16,8,wmma::precision::tf32,wmma::col_major> FragBT;
typedef wmma::fragment<wmma::accumulator,16,16,8,float> FragC;

// ---------------------------------------------------------------------------
// Small GEMMs (M=8192, N=512, K=512): C = act(A @ B + bias), tf32x3 accuracy.
// BM=64, BN=128, BK=32, 256 threads, warp grid 4(M) x 2(N), warp tile 16x64.
// hi/lo split done ONCE at SMEM store; fragments load pre-split tiles.
// Dynamic smem: Ah/Al 64x40 x2 + Bh/Bl 32x136 x2 + Cs 64x136 = 90112 B (2 CTA/SM).
// ---------------------------------------------------------------------------
template<int ACT, int ROUND>
__global__ void __launch_bounds__(256) gemm_x3_kernel(
    const float* __restrict__ A, const float* __restrict__ B,
    const float* __restrict__ bias, float* __restrict__ C)
{
    extern __shared__ float sm[];
    float (*Ah)[40]  = (float(*)[40]) (sm);
    float (*Al)[40]  = (float(*)[40]) (sm + 2560);
    float (*Bh)[136] = (float(*)[136])(sm + 5120);
    float (*Bl)[136] = (float(*)[136])(sm + 9472);
    float (*Cs)[136] = (float(*)[136])(sm + 13824);

    const int tid = threadIdx.x;
    const int w = tid >> 5, wm = w >> 1, wn = w & 1;
    const int bm = blockIdx.x * 64, bn = blockIdx.y * 128;

    FragC acc[4];
    #pragma unroll
    for (int i = 0; i < 4; i++) wmma::fill_fragment(acc[i], 0.f);

    // A loader: idx = tid + p*256 -> r = idx>>3 (0..63), c4 = (idx&7)*4
    // B loader: idx = tid + p*256 -> r = idx>>5 (0..31), c4 = (idx&31)*4
    float4 apre[2], bpre[4];
    #pragma unroll
    for (int p = 0; p < 2; p++) {
        int idx = tid + p*256, r = idx >> 3, c4 = (idx & 7) * 4;
        apre[p] = *(const float4*)&A[(size_t)(bm + r)*DIM + c4];
    }
    #pragma unroll
    for (int p = 0; p < 4; p++) {
        int idx = tid + p*256, r = idx >> 5, c4 = (idx & 31) * 4;
        bpre[p] = *(const float4*)&B[(size_t)r*DIM + bn + c4];
    }

    #pragma unroll 1
    for (int kt = 0; kt < 16; kt++) {
        if (kt > 0) __syncthreads();
        // split + store current chunk
        #pragma unroll
        for (int p = 0; p < 2; p++) {
            int idx = tid + p*256, r = idx >> 3, c4 = (idx & 7) * 4;
            float vv[4] = {apre[p].x, apre[p].y, apre[p].z, apre[p].w};
            #pragma unroll
            for (int e = 0; e < 4; e++) {
                float h = wmma::__float_to_tf32(vv[e]);
                Ah[r][c4+e] = h;
                Al[r][c4+e] = wmma::__float_to_tf32(vv[e] - h);
            }
        }
        #pragma unroll
        for (int p = 0; p < 4; p++) {
            int idx = tid + p*256, r = idx >> 5, c4 = (idx & 31) * 4;
            float vv[4] = {bpre[p].x, bpre[p].y, bpre[p].z, bpre[p].w};
            #pragma unroll
            for (int e = 0; e < 4; e++) {
                float h = wmma::__float_to_tf32(vv[e]);
                Bh[r][c4+e] = h;
                Bl[r][c4+e] = wmma::__float_to_tf32(vv[e] - h);
            }
        }
        __syncthreads();
        // prefetch next chunk (overlaps with compute below)
        if (kt < 15) {
            #pragma unroll
            for (int p = 0; p < 2; p++) {
                int idx = tid + p*256, r = idx >> 3, c4 = (idx & 7) * 4;
                apre[p] = *(const float4*)&A[(size_t)(bm + r)*DIM + (kt+1)*32 + c4];
            }
            #pragma unroll
            for (int p = 0; p < 4; p++) {
                int idx = tid + p*256, r = idx >> 5, c4 = (idx & 31) * 4;
                bpre[p] = *(const float4*)&B[(size_t)((kt+1)*32 + r)*DIM + bn + c4];
            }
        }
        // compute
        #pragma unroll
        for (int ks = 0; ks < 4; ks++) {
            FragA ah, al;
            wmma::load_matrix_sync(ah, &Ah[wm*16][ks*8], 40);
            wmma::load_matrix_sync(al, &Al[wm*16][ks*8], 40);
            #pragma unroll
            for (int nf = 0; nf < 4; nf++) {
                FragB bh, bl;
                wmma::load_matrix_sync(bh, &Bh[ks*8][wn*64 + nf*16], 136);
                wmma::load_matrix_sync(bl, &Bl[ks*8][wn*64 + nf*16], 136);
                wmma::mma_sync(acc[nf], ah, bh, acc[nf]);
                wmma::mma_sync(acc[nf], al, bh, acc[nf]);
                wmma::mma_sync(acc[nf], ah, bl, acc[nf]);
            }
        }
    }

    __syncthreads();
    #pragma unroll
    for (int nf = 0; nf < 4; nf++)
        wmma::store_matrix_sync(&Cs[wm*16][wn*64 + nf*16], acc[nf], 136,
                                wmma::mem_row_major);
    __syncthreads();

    #pragma unroll
    for (int p = 0; p < 32; p++) {
        int idx = tid + p*256;
        int r = idx >> 7, c = idx & 127;
        float v = Cs[r][c] + bias[bn + c];
        if (ACT == 1) v = 0.5f * v * (1.0f + erff(v * 0.70710678118654752f));
        if (ROUND == 1) v = wmma::__float_to_tf32(v);
        C[(size_t)(bm + r)*DIM + bn + c] = v;
    }
}

// ---------------------------------------------------------------------------
// Fused retention: O = (D .* (Q @ K^T)) @ V without materializing inter.
// One CTA per 64-row Q block; 512 threads, 16 warps (warp grid 4x4).
// Q/K/V arrive pre-rounded to tf32; S rounded once during the D pass.
// K chunks double-buffered via register prefetch.
// Dynamic smem: Qf 64x520 + Ks[2]64x72 + Ss 64x72 + Vs 16x520 = 221696 B.
// ---------------------------------------------------------------------------
__global__ void __launch_bounds__(512) retention_kernel(
    const float* __restrict__ Q, const float* __restrict__ Kmat,
    const float* __restrict__ V, const float* __restrict__ D,
    float* __restrict__ O)
{
    extern __shared__ float sm[];
    float (*Qf)[520]    = (float(*)[520])   (sm);           // 33280 floats
    float (*Ks)[64][72] = (float(*)[64][72])(sm + 33280);   //  9216
    float (*Ss)[72]     = (float(*)[72])    (sm + 42496);   //  4608
    float (*Vs)[520]    = (float(*)[520])   (sm + 47104);   //  8320

    const int tid = threadIdx.x;
    const int w = tid >> 5, wm = w >> 2, wn = w & 3;
    const int i0 = blockIdx.x * 64;

    // Load full Q tile (64 x 512), already tf32-rounded by producer.
    #pragma unroll
    for (int p = 0; p < 16; p++) {
        int idx = tid + p*512;
        int r = idx >> 7, c4 = (idx & 127) * 4;
        *(float4*)&Qf[r][c4] = *(const float4*)&Q[(size_t)(i0 + r)*DIM + c4];
    }

    FragC o[8];
    #pragma unroll
    for (int i = 0; i < 8; i++) wmma::fill_fragment(o[i], 0.f);

    #pragma unroll 1
    for (int j0 = 0; j0 < NROWS; j0 += 64) {
        // ---- S = Q_tile @ K_j^T (64x64), each warp one 16x16 tile ----
        FragC s;
        wmma::fill_fragment(s, 0.f);

        float4 kpre[2];
        #pragma unroll
        for (int p = 0; p < 2; p++) {
            int idx = tid + p*512, r = idx >> 4, c4 = (idx & 15) * 4;
            kpre[p] = *(const float4*)&Kmat[(size_t)(j0 + r)*DIM + c4];
        }
        #pragma unroll
        for (int p = 0; p < 2; p++) {
            int idx = tid + p*512, r = idx >> 4, c4 = (idx & 15) * 4;
            *(float4*)&Ks[0][r][c4] = kpre[p];
        }
        __syncthreads();

        #pragma unroll 1
        for (int c = 0; c < 8; c++) {
            int buf = c & 1;
            if (c < 7) {
                #pragma unroll
                for (int p = 0; p < 2; p++) {
                    int idx = tid + p*512, r = idx >> 4, c4 = (idx & 15) * 4;
                    kpre[p] = *(const float4*)&Kmat[(size_t)(j0 + r)*DIM + (c+1)*64 + c4];
                }
            }
            #pragma unroll
            for (int ks = 0; ks < 8; ks++) {
                FragA a;
                wmma::load_matrix_sync(a, &Qf[wm*16][c*64 + ks*8], 520);
                FragBT b;   // B[k][n] = K[j0 + wn*16 + n][...] -> col-major on Ks rows
                wmma::load_matrix_sync(b, &Ks[buf][wn*16][ks*8], 72);
                wmma::mma_sync(s, a, b, s);
            }
            if (c < 7) {
                #pragma unroll
                for (int p = 0; p < 2; p++) {
                    int idx = tid + p*512, r = idx >> 4, c4 = (idx & 15) * 4;
                    *(float4*)&Ks[buf ^ 1][r][c4] = kpre[p];
                }
            }
            __syncthreads();
        }

        wmma::store_matrix_sync(&Ss[wm*16][wn*16], s, 72, wmma::mem_row_major);
        __syncthreads();

        // ---- S *= D tile; round once to tf32 ----
        #pragma unroll
        for (int q = 0; q < 8; q++) {
            int idx = tid + q*512;
            int r = idx >> 6, cc = idx & 63;
            float v = Ss[r][cc] * D[(size_t)(i0 + r)*NROWS + j0 + cc];
            Ss[r][cc] = wmma::__float_to_tf32(v);
        }
        __syncthreads();

        // ---- O += S_d (64x64) @ V_j (64x512); each warp 16x128 of O ----
        #pragma unroll 1
        for (int kc = 0; kc < 4; kc++) {
            if (kc > 0) __syncthreads();
            #pragma unroll
            for (int p = 0; p < 4; p++) {
                int idx = tid + p*512;
                int r = idx >> 7, c4 = (idx & 127) * 4;
                *(float4*)&Vs[r][c4] =
                    *(const float4*)&V[(size_t)(j0 + kc*16 + r)*DIM + c4];
            }
            __syncthreads();
            #pragma unroll
            for (int ks = 0; ks < 2; ks++) {
                FragA a;
                wmma::load_matrix_sync(a, &Ss[wm*16][kc*16 + ks*8], 72);
                #pragma unroll
                for (int nf = 0; nf < 8; nf++) {
                    FragB b;
                    wmma::load_matrix_sync(b, &Vs[ks*8][wn*128 + nf*16], 520);
                    wmma::mma_sync(o[nf], a, b, o[nf]);
                }
            }
        }
        __syncthreads();
    }

    #pragma unroll
    for (int nf = 0; nf < 8; nf++)
        wmma::store_matrix_sync(&O[(size_t)(i0 + wm*16)*DIM + wn*128 + nf*16],
                                o[nf], DIM, wmma::mem_row_major);
}

// ---------------------------------------------------------------------------
// GroupNorm over 16 groups of 32 channels, per row, in-place on d_out.
// ---------------------------------------------------------------------------
__global__ void groupnorm_kernel(float* __restrict__ out,
                                 const float* __restrict__ gamma,
                                 const float* __restrict__ beta)
{
    __shared__ float buf[512];
    __shared__ float smu[16], siv[16];
    const int row = blockIdx.x;
    const int tid = threadIdx.x;  // 256
    float* p = out + (size_t)row * DIM;
    buf[tid]       = p[tid];
    buf[tid + 256] = p[tid + 256];
    __syncthreads();
    if (tid < 16) {
        float s = 0.f, s2 = 0.f;
        #pragma unroll
        for (int c = 0; c < 32; c++) {
            float v = buf[tid*32 + c];
            s += v; s2 += v*v;
        }
        float mu  = s  * (1.f/32.f);
        float var = s2 * (1.f/32.f) - mu*mu;
        smu[tid] = mu;
        siv[tid] = rsqrtf(var + 1e-5f);
    }
    __syncthreads();
    #pragma unroll
    for (int q = 0; q < 2; q++) {
        int c = tid + q*256;
        int g = c >> 5;
        p[c] = (buf[c] - smu[g]) * siv[g] * gamma[c] + beta[c];
    }
}

// ---------------------------------------------------------------------------
extern "C" void kernel_launch(void* const* d_in, const int* in_sizes, int n_in,
                              void* d_out, int out_size)
{
    const float* x     = (const float*)d_in[0];
    const float* D     = (const float*)d_in[1];
    const float* Wq    = (const float*)d_in[2];
    const float* bq    = (const float*)d_in[3];
    const float* Wk    = (const float*)d_in[4];
    const float* bk    = (const float*)d_in[5];
    const float* Wv    = (const float*)d_in[6];
    const float* bv    = (const float*)d_in[7];
    const float* Wf    = (const float*)d_in[8];
    const float* bf    = (const float*)d_in[9];
    const float* Wp    = (const float*)d_in[10];
    const float* bp    = (const float*)d_in[11];
    const float* gamma = (const float*)d_in[12];
    const float* beta  = (const float*)d_in[13];
    float* out = (float*)d_out;

    float *Q, *K, *V, *XR, *H;
    cudaGetSymbolAddress((void**)&Q,  g_Q);
    cudaGetSymbolAddress((void**)&K,  g_K);
    cudaGetSymbolAddress((void**)&V,  g_V);
    cudaGetSymbolAddress((void**)&XR, g_XR);
    cudaGetSymbolAddress((void**)&H,  g_H);

    const int GEMM_SMEM = 90112;
    const int RET_SMEM  = 221696;
    cudaFuncSetAttribute(gemm_x3_kernel<0,1>,
                         cudaFuncAttributeMaxDynamicSharedMemorySize, GEMM_SMEM);
    cudaFuncSetAttribute(gemm_x3_kernel<1,0>,
                         cudaFuncAttributeMaxDynamicSharedMemorySize, GEMM_SMEM);
    cudaFuncSetAttribute(gemm_x3_kernel<0,0>,
                         cudaFuncAttributeMaxDynamicSharedMemorySize, GEMM_SMEM);
    cudaFuncSetAttribute(retention_kernel,
                         cudaFuncAttributeMaxDynamicSharedMemorySize, RET_SMEM);

    dim3 gs(NROWS/64, DIM/128);   // 128 x 4
    gemm_x3_kernel<0,1><<<gs, 256, GEMM_SMEM>>>(x, Wq, bq, Q);
    gemm_x3_kernel<0,1><<<gs, 256, GEMM_SMEM>>>(x, Wk, bk, K);
    gemm_x3_kernel<0,1><<<gs, 256, GEMM_SMEM>>>(x, Wv, bv, V);

    retention_kernel<<<NROWS/64, 512, RET_SMEM>>>(Q, K, V, D, XR);

    gemm_x3_kernel<1,0><<<gs, 256, GEMM_SMEM>>>(XR, Wf, bf, H);    // + exact GELU
    gemm_x3_kernel<0,0><<<gs, 256, GEMM_SMEM>>>(H,  Wp, bp, out);

    groupnorm_kernel<<<NROWS, 256>>>(out, gamma, beta);
}